// round 13
// baseline (speedup 1.0000x reference)
#include <cuda_runtime.h>
#include <cstdint>

// Problem constants (fixed shapes for ClusterLoss_82317343195278)
#define NROWS 65536
#define DLAT  64
#define KC    64
#define DDATA 512
#define NB    256   // kmeans blocks; TPB tiles of 128 rows each
#define TPB   2
#define NITERS 10

// ---- strides (in floats) ----
// SE=76: GEMM1 A (gid*76+tig -> gid*12+tig mod32 unique) AND GEMM2 B
//        (tig*76+gid -> tig*12+gid mod32 unique) both conflict-free.
#define SE 76
#define SC 68   // GEMM1 B: gid*68+tig -> gid*4+tig mod32 unique
#define SR 72   // GEMM2 A: tig*72+gid -> tig*8+gid mod32 unique

// ---- dynamic smem layout (bytes) ----
#define SM_E    0u
#define SM_C    (SM_E + 128u * SE * 4u)          // 38912
#define SM_R    (SM_C + 64u * SC * 4u)           // 56320
#define SM_SC2  (SM_R + 128u * SR * 4u)          // 93184
#define SM_SRS  (SM_SC2 + 256u)                  // 93440
#define SM_SRED (SM_SRS + 256u)                  // 93696
#define SM_TOTAL (SM_SRED + 1024u)               // 94720  (2 CTAs/SM)

// ---- tf32 helpers ----
__device__ __forceinline__ uint32_t tf32b(float x) {
    uint32_t u;
    asm("cvt.rna.tf32.f32 %0, %1;" : "=r"(u) : "f"(x));
    return u;
}
// mma.sync m16n8k8 tf32: D += A*B (D,C same regs)
__device__ __forceinline__ void mma8(float* d, const uint32_t* a, const uint32_t* b) {
    asm volatile(
        "mma.sync.aligned.m16n8k8.row.col.f32.tf32.tf32.f32 "
        "{%0,%1,%2,%3}, {%4,%5,%6,%7}, {%8,%9}, {%0,%1,%2,%3};"
        : "+f"(d[0]), "+f"(d[1]), "+f"(d[2]), "+f"(d[3])
        : "r"(a[0]), "r"(a[1]), "r"(a[2]), "r"(a[3]), "r"(b[0]), "r"(b[1]));
}

// ---- global scratch ----
__device__ __align__(16) float g_C[KC * DLAT];            // centroids [k][d]
__device__ __align__(16) float g_x2[NROWS];
__device__ __align__(16) uint32_t g_encT[NROWS * DLAT];   // enc pre-converted to tf32
__device__ __align__(16) float g_partC[NB][KC * DLAT];    // [b][k*64+d]
__device__ __align__(16) float g_partR[NB][KC];
__device__ float g_lossSum;
__device__ float g_decSum;

// ---------------------------------------------------------------------------
// Init: x2 per row, tf32-converted enc, C = enc[:K], zero accumulators
// ---------------------------------------------------------------------------
__global__ void init_kernel(const float* __restrict__ enc) {
    int g = blockIdx.x * blockDim.x + threadIdx.x;  // one thread per row
    const float4* p = reinterpret_cast<const float4*>(enc) + (size_t)g * (DLAT / 4);
    uint4* q = reinterpret_cast<uint4*>(g_encT) + (size_t)g * (DLAT / 4);
    float s = 0.f;
#pragma unroll
    for (int i = 0; i < DLAT / 4; i++) {
        float4 v = p[i];
        s += v.x * v.x + v.y * v.y + v.z * v.z + v.w * v.w;
        q[i] = make_uint4(tf32b(v.x), tf32b(v.y), tf32b(v.z), tf32b(v.w));
    }
    g_x2[g] = s;
    if (g < KC * DLAT) g_C[g] = enc[g];
    if (g == 0) { g_lossSum = 0.f; g_decSum = 0.f; }
}

__global__ void decoder_kernel(const float4* __restrict__ X,
                               const float4* __restrict__ Dc, int n4) {
    int i = blockIdx.x * blockDim.x + threadIdx.x;
    int stride = gridDim.x * blockDim.x;
    float s = 0.f;
    for (; i < n4; i += stride) {
        float4 a = X[i], b = Dc[i];
        float dx = a.x - b.x, dy = a.y - b.y, dz = a.z - b.z, dw = a.w - b.w;
        s += dx * dx + dy * dy + dz * dz + dw * dw;
    }
    __shared__ float red[256];
    red[threadIdx.x] = s;
    __syncthreads();
#pragma unroll
    for (int o = 128; o > 0; o >>= 1) {
        if (threadIdx.x < o) red[threadIdx.x] += red[threadIdx.x + o];
        __syncthreads();
    }
    if (threadIdx.x == 0) atomicAdd(&g_decSum, red[0]);
}

// ---------------------------------------------------------------------------
// kmeans iteration: both GEMMs on mma.sync tf32, single-pass.
// 8 warps; GEMM1: warp w owns rows [16w,16w+16) x all 64 clusters.
// GEMM2: warp w owns clusters [(w&3)*16,+16) x d-tiles [(w>>2)*32,+32).
// Last iteration (doLoss): loss only, GEMM2/partials skipped.
// ---------------------------------------------------------------------------
__global__ void __launch_bounds__(256, 2)
kmeans_iter(int doLoss) {
    extern __shared__ __align__(16) char smem[];
    uint32_t* sE = (uint32_t*)(smem + SM_E);
    uint32_t* sC = (uint32_t*)(smem + SM_C);
    uint32_t* sR = (uint32_t*)(smem + SM_R);
    float* sc2  = (float*)(smem + SM_SC2);
    float* srs  = (float*)(smem + SM_SRS);
    float* sred = (float*)(smem + SM_SRED);

    const int tid = threadIdx.x;
    const int w = tid >> 5, lane = tid & 31;
    const int gid = lane >> 2, tig = lane & 3;

    // ---- load C as tf32 (stride SC) + c2 (fp32) + zero srs ----
#pragma unroll
    for (int i = 0; i < 4; i++) {
        int idx = tid + i * 256;             // over 1024 float4
        int k = idx >> 4, d4 = (idx & 15) * 4;
        float4 c = *(const float4*)&g_C[k * DLAT + d4];
        *(uint4*)&sC[k * SC + d4] =
            make_uint4(tf32b(c.x), tf32b(c.y), tf32b(c.z), tf32b(c.w));
    }
    if (tid < KC) {
        float s = 0.f;
        const float4* cr = (const float4*)&g_C[tid * DLAT];
#pragma unroll
        for (int i = 0; i < 16; i++) {
            float4 c = cr[i];
            s += c.x * c.x + c.y * c.y + c.z * c.z + c.w * c.w;
        }
        sc2[tid] = s;
        srs[tid] = 0.f;
    }

    float acc2[4][4];
#pragma unroll
    for (int j = 0; j < 4; j++)
#pragma unroll
        for (int i = 0; i < 4; i++) acc2[j][i] = 0.f;
    float lossAcc = 0.f;

#pragma unroll 1
    for (int t = 0; t < TPB; t++) {
        const int rowBase = (blockIdx.x * TPB + t) * 128;
        __syncthreads();  // C stores (t=0) / previous GEMM2 reads done

        // ---- load enc tile (already tf32) into stride-SE smem ----
        {
            const uint4* src = (const uint4*)(g_encT + (size_t)rowBase * DLAT);
#pragma unroll
            for (int i = 0; i < 8; i++) {
                int idx = tid + i * 256;     // over 2048 uint4
                int row = idx >> 4, d4 = (idx & 15) * 4;
                *(uint4*)&sE[row * SE + d4] = src[idx];
            }
        }
        __syncthreads();

        // ---- GEMM1: rows [16w,16w+16) x 64 clusters, K=64 in 8 chunks ----
        float acc1[8][4];
#pragma unroll
        for (int n = 0; n < 8; n++)
#pragma unroll
            for (int i = 0; i < 4; i++) acc1[n][i] = 0.f;
        const int r0 = w * 16;
#pragma unroll
        for (int dc = 0; dc < 8; dc++) {
            uint32_t a[4];
            const int ab = (r0 + gid) * SE + dc * 8 + tig;
            a[0] = sE[ab];
            a[1] = sE[ab + 8 * SE];
            a[2] = sE[ab + 4];
            a[3] = sE[ab + 8 * SE + 4];
#pragma unroll
            for (int n = 0; n < 8; n++) {
                uint32_t b[2];
                const int bb = (n * 8 + gid) * SC + dc * 8 + tig;
                b[0] = sC[bb];
                b[1] = sC[bb + 4];
                mma8(acc1[n], a, b);
            }
        }

        // ---- epilogue: d2 -> exp (cached in acc1), softmax, loss or r/colsum ----
        {
            const int rowA = rowBase + r0 + gid;
            const float x2a = g_x2[rowA], x2b = g_x2[rowA + 8];
#pragma unroll
            for (int n = 0; n < 8; n++) {
                const float c20 = sc2[n * 8 + 2 * tig];
                const float c21 = sc2[n * 8 + 2 * tig + 1];
                float v;
                v = x2a + c20 - 2.f * acc1[n][0]; acc1[n][0] = v > 0.f ? v : 0.f;
                v = x2a + c21 - 2.f * acc1[n][1]; acc1[n][1] = v > 0.f ? v : 0.f;
                v = x2b + c20 - 2.f * acc1[n][2]; acc1[n][2] = v > 0.f ? v : 0.f;
                v = x2b + c21 - 2.f * acc1[n][3]; acc1[n][3] = v > 0.f ? v : 0.f;
            }
            float cs[16];
            const int rlA = r0 + gid;
            // two half-rows: h=0 -> rowA (acc1[n][0..1]), h=1 -> rowB (acc1[n][2..3])
#pragma unroll
            for (int h = 0; h < 2; h++) {
                float mn = 3.4e38f;
#pragma unroll
                for (int n = 0; n < 8; n++)
                    mn = fminf(mn, fminf(acc1[n][2 * h], acc1[n][2 * h + 1]));
                mn = fminf(mn, __shfl_xor_sync(0xffffffffu, mn, 1));
                mn = fminf(mn, __shfl_xor_sync(0xffffffffu, mn, 2));
                float es = 0.f, ed2 = 0.f;
#pragma unroll
                for (int n = 0; n < 8; n++) {
                    float d20 = acc1[n][2 * h], d21 = acc1[n][2 * h + 1];
                    float e0 = __expf(mn - d20);
                    float e1 = __expf(mn - d21);
                    es += e0 + e1;
                    ed2 += e0 * d20 + e1 * d21;
                    acc1[n][2 * h] = e0;      // cache exp, d2 no longer needed
                    acc1[n][2 * h + 1] = e1;
                }
                es += __shfl_xor_sync(0xffffffffu, es, 1);
                es += __shfl_xor_sync(0xffffffffu, es, 2);
                const float inv = __fdividef(1.f, es);
                if (doLoss) {
                    float ls = ed2 * inv;
                    ls += __shfl_xor_sync(0xffffffffu, ls, 1);
                    ls += __shfl_xor_sync(0xffffffffu, ls, 2);
                    if (tig == 0) lossAcc += ls;
                } else {
#pragma unroll
                    for (int n = 0; n < 8; n++) {
                        float rr0 = acc1[n][2 * h] * inv;
                        float rr1 = acc1[n][2 * h + 1] * inv;
                        if (h == 0) { cs[2 * n] = rr0; cs[2 * n + 1] = rr1; }
                        else        { cs[2 * n] += rr0; cs[2 * n + 1] += rr1; }
                        *(uint2*)&sR[(rlA + 8 * h) * SR + n * 8 + 2 * tig] =
                            make_uint2(tf32b(rr0), tf32b(rr1));
                    }
                }
            }
            if (!doLoss) {
                // column sums of r over this warp's 16 rows -> shared atomics
#pragma unroll
                for (int i = 0; i < 16; i++) {
                    cs[i] += __shfl_xor_sync(0xffffffffu, cs[i], 4);
                    cs[i] += __shfl_xor_sync(0xffffffffu, cs[i], 8);
                    cs[i] += __shfl_xor_sync(0xffffffffu, cs[i], 16);
                }
                if (gid == 0) {
#pragma unroll
                    for (int n = 0; n < 8; n++) {
                        atomicAdd(&srs[n * 8 + 2 * tig],     cs[2 * n]);
                        atomicAdd(&srs[n * 8 + 2 * tig + 1], cs[2 * n + 1]);
                    }
                }
            }
        }

        if (!doLoss) {
            __syncthreads();  // all r tiles written before GEMM2 reads

            // ---- GEMM2: clusters [(w&3)*16,+16) x d [(w>>2)*32,+32), K=128 ----
            const int m0 = (w & 3) * 16;
            const int nb4 = (w >> 2) * 4;
#pragma unroll
            for (int rc = 0; rc < 16; rc++) {
                uint32_t a[4];
                const int ar = (rc * 8 + tig) * SR + m0 + gid;
                const int ar4 = ar + 4 * SR;
                a[0] = sR[ar];
                a[1] = sR[ar + 8];
                a[2] = sR[ar4];
                a[3] = sR[ar4 + 8];
#pragma unroll
                for (int j = 0; j < 4; j++) {
                    uint32_t b[2];
                    const int be = (rc * 8 + tig) * SE + (nb4 + j) * 8 + gid;
                    b[0] = sE[be];
                    b[1] = sE[be + 4 * SE];
                    mma8(acc2[j], a, b);
                }
            }
        }
    }

    if (!doLoss) {
        // ---- write per-block partials ----
        const int m0 = (w & 3) * 16;
        const int nb4 = (w >> 2) * 4;
#pragma unroll
        for (int j = 0; j < 4; j++) {
            const int n0 = (nb4 + j) * 8;
            const int kA = m0 + gid, kB = kA + 8;
            const int col = n0 + 2 * tig;
            *(float2*)&g_partC[blockIdx.x][kA * DLAT + col] =
                make_float2(acc2[j][0], acc2[j][1]);
            *(float2*)&g_partC[blockIdx.x][kB * DLAT + col] =
                make_float2(acc2[j][2], acc2[j][3]);
        }
        __syncthreads();
        if (tid < KC) g_partR[blockIdx.x][tid] = srs[tid];
    } else {
        sred[tid] = lossAcc;
        __syncthreads();
        for (int o = 128; o > 0; o >>= 1) {
            if (tid < o) sred[tid] += sred[tid + o];
            __syncthreads();
        }
        if (tid == 0) atomicAdd(&g_lossSum, sred[0]);
    }
}

// ---------------------------------------------------------------------------
// Centroid update, vectorized: 256 blocks (k x d-quarter) x 256 threads.
// Thread (brow=t>>2, lane=t&3): sums 4 float4 loads over b = brow+64j,
// float4 smem tree over brow. 4 MB L2-resident traffic, MLP=4.
// ---------------------------------------------------------------------------
__global__ void __launch_bounds__(256) update_kernel() {
    const int k = blockIdx.x >> 2;
    const int dq = blockIdx.x & 3;
    const int tid = threadIdx.x;
    const int lane = tid & 3, brow = tid >> 2;
    __shared__ float sden[256];
    __shared__ float4 sacc[256];

    // denom: 256 threads each grab one partial of colsum(r)
    sden[tid] = g_partR[tid][k];

    const int dcol = k * DLAT + dq * 16 + lane * 4;
    float4 a = make_float4(0.f, 0.f, 0.f, 0.f);
#pragma unroll
    for (int j = 0; j < 4; j++) {
        float4 v = *(const float4*)&g_partC[brow + 64 * j][dcol];
        a.x += v.x; a.y += v.y; a.z += v.z; a.w += v.w;
    }
    sacc[tid] = a;
    __syncthreads();
#pragma unroll
    for (int o = 128; o > 0; o >>= 1) {
        if (tid < o) {
            sden[tid] += sden[tid + o];
            if (o >= 4) {
                float4 u = sacc[tid], v = sacc[tid + o];
                sacc[tid] = make_float4(u.x + v.x, u.y + v.y, u.z + v.z, u.w + v.w);
            }
        }
        __syncthreads();
    }
    if (tid < 4) {
        const float inv = __fdividef(1.f, sden[0] + 1e-8f);
        float4 v = sacc[tid];
        *(float4*)&g_C[k * DLAT + dq * 16 + tid * 4] =
            make_float4(v.x * inv, v.y * inv, v.z * inv, v.w * inv);
    }
}

__global__ void finalize_kernel(float* out) {
    out[0] = g_decSum * (1.f / ((float)NROWS * (float)DDATA))
           + 0.001f * g_lossSum * (1.f / (float)NROWS);
}

// ---------------------------------------------------------------------------
extern "C" void kernel_launch(void* const* d_in, const int* in_sizes, int n_in,
                              void* d_out, int out_size) {
    const float* X   = (const float*)d_in[0];
    const float* enc = (const float*)d_in[1];
    const float* dec = (const float*)d_in[2];
    float* out = (float*)d_out;

    cudaFuncSetAttribute(kmeans_iter, cudaFuncAttributeMaxDynamicSharedMemorySize,
                         SM_TOTAL);

    init_kernel<<<NROWS / 256, 256>>>(enc);

    const int n4 = NROWS * DDATA / 4;
    decoder_kernel<<<1024, 256>>>((const float4*)X, (const float4*)dec, n4);

    for (int it = 0; it < NITERS; it++) {
        kmeans_iter<<<NB, 256, SM_TOTAL>>>(it == NITERS - 1 ? 1 : 0);
        if (it < NITERS - 1) update_kernel<<<NB, 256>>>();
    }

    finalize_kernel<<<1, 1>>>(out);
}

// round 14
// speedup vs baseline: 1.0609x; 1.0609x over previous
#include <cuda_runtime.h>
#include <cstdint>

// Problem constants (fixed shapes for ClusterLoss_82317343195278)
#define NROWS 65536
#define DLAT  64
#define KC    64
#define DDATA 512
#define NB    256   // kmeans blocks; TPB tiles of 128 rows each
#define TPB   2
#define NITERS 10

// ---- strides (in floats) ----
// SE=76: GEMM1 A (gid*76+tig -> gid*12+tig mod32 unique) AND GEMM2 B
//        (tig*76+gid -> tig*12+gid mod32 unique) both conflict-free.
#define SE 76
#define SC 68   // GEMM1 B: gid*68+tig -> gid*4+tig mod32 unique
#define SR 72   // GEMM2 A: tig*72+gid -> tig*8+gid mod32 unique

// ---- dynamic smem layout (bytes) ----
#define SM_E    0u
#define SM_C    (SM_E + 128u * SE * 4u)          // 38912
#define SM_R    (SM_C + 64u * SC * 4u)           // 56320
#define SM_SC2  (SM_R + 128u * SR * 4u)          // 93184
#define SM_SRS  (SM_SC2 + 256u)                  // 93440
#define SM_SINV (SM_SRS + 256u)                  // 93696
#define SM_SRED (SM_SINV + 256u)                 // 93952
#define SM_TOTAL (SM_SRED + 1024u)               // 94976  (2 CTAs/SM)

// ---- tf32 helpers ----
__device__ __forceinline__ uint32_t tf32b(float x) {
    uint32_t u;
    asm("cvt.rna.tf32.f32 %0, %1;" : "=r"(u) : "f"(x));
    return u;
}
// mma.sync m16n8k8 tf32: D += A*B (D,C same regs)
__device__ __forceinline__ void mma8(float* d, const uint32_t* a, const uint32_t* b) {
    asm volatile(
        "mma.sync.aligned.m16n8k8.row.col.f32.tf32.tf32.f32 "
        "{%0,%1,%2,%3}, {%4,%5,%6,%7}, {%8,%9}, {%0,%1,%2,%3};"
        : "+f"(d[0]), "+f"(d[1]), "+f"(d[2]), "+f"(d[3])
        : "r"(a[0]), "r"(a[1]), "r"(a[2]), "r"(a[3]), "r"(b[0]), "r"(b[1]));
}

// ---- global scratch ----
// Triple-buffered centroid accumulators. Iter t: reads buf (t+2)%3,
// writes buf t%3, zeroes buf (t+1)%3 (consumed at iter t-1; kernel
// boundaries provide all ordering). Init seeds buf 2 (acc=enc[:K], den=1)
// and zeroes buf 0 (iter 0's output).
__device__ __align__(16) float g_accC[3][KC * DLAT];
__device__ float g_accR[3][KC];
__device__ __align__(16) float g_x2[NROWS];
__device__ float g_lossSum;
__device__ float g_decSum;

// ---------------------------------------------------------------------------
// Init: x2 per row, seed centroid buffers, zero scalars
// ---------------------------------------------------------------------------
__global__ void init_kernel(const float* __restrict__ enc) {
    int g = blockIdx.x * blockDim.x + threadIdx.x;  // one thread per row
    const float4* p = reinterpret_cast<const float4*>(enc) + (size_t)g * (DLAT / 4);
    float s = 0.f;
#pragma unroll
    for (int i = 0; i < DLAT / 4; i++) {
        float4 v = p[i];
        s += v.x * v.x + v.y * v.y + v.z * v.z + v.w * v.w;
    }
    g_x2[g] = s;
    if (g < KC * DLAT) {
        g_accC[2][g] = enc[g];   // seed: C0 = enc[:K]  (den=1 -> exact)
        g_accC[0][g] = 0.f;      // iter 0 output buffer
    }
    if (g < KC) {
        g_accR[2][g] = 1.0f;     // 1 + 1e-8f rounds to 1.0f in fp32
        g_accR[0][g] = 0.f;
    }
    if (g == 0) { g_lossSum = 0.f; g_decSum = 0.f; }
}

__global__ void decoder_kernel(const float4* __restrict__ X,
                               const float4* __restrict__ Dc, int n4) {
    int i = blockIdx.x * blockDim.x + threadIdx.x;
    int stride = gridDim.x * blockDim.x;
    float s = 0.f;
    for (; i < n4; i += stride) {
        float4 a = X[i], b = Dc[i];
        float dx = a.x - b.x, dy = a.y - b.y, dz = a.z - b.z, dw = a.w - b.w;
        s += dx * dx + dy * dy + dz * dz + dw * dw;
    }
    __shared__ float red[256];
    red[threadIdx.x] = s;
    __syncthreads();
#pragma unroll
    for (int o = 128; o > 0; o >>= 1) {
        if (threadIdx.x < o) red[threadIdx.x] += red[threadIdx.x + o];
        __syncthreads();
    }
    if (threadIdx.x == 0) atomicAdd(&g_decSum, red[0]);
}

// ---------------------------------------------------------------------------
// kmeans iteration: both GEMMs on mma.sync tf32, single-pass.
// C is materialized on the fly from accC[prev]/(accR[prev]+eps).
// Output partials accumulated via global atomics into accC[cur]/accR[cur].
// Last iteration (doLoss): loss only, GEMM2/accumulation skipped.
// ---------------------------------------------------------------------------
__global__ void __launch_bounds__(256, 2)
kmeans_iter(const float* __restrict__ enc, int prevB, int curB, int zeroB,
            int doLoss) {
    extern __shared__ __align__(16) char smem[];
    uint32_t* sE = (uint32_t*)(smem + SM_E);
    uint32_t* sC = (uint32_t*)(smem + SM_C);
    uint32_t* sR = (uint32_t*)(smem + SM_R);
    float* sc2  = (float*)(smem + SM_SC2);
    float* srs  = (float*)(smem + SM_SRS);
    float* sInv = (float*)(smem + SM_SINV);
    float* sred = (float*)(smem + SM_SRED);

    const int tid = threadIdx.x;
    const int w = tid >> 5, lane = tid & 31;
    const int gid = lane >> 2, tig = lane & 3;

    // ---- zero next-iteration's accumulator slice (no ordering needed:
    //      zeroB was consumed one kernel ago, written one kernel ahead) ----
    if (tid < 16) g_accC[zeroB][blockIdx.x * 16 + tid] = 0.f;
    if (tid == 16 && blockIdx.x < KC) g_accR[zeroB][blockIdx.x] = 0.f;

    // ---- per-cluster inverse denominator ----
    if (tid < KC) sInv[tid] = __fdividef(1.f, g_accR[prevB][tid] + 1e-8f);
    __syncthreads();

    // ---- materialize C = accC*inv as tf32 (stride SC); c2 in fp32; zero srs ----
#pragma unroll
    for (int i = 0; i < 4; i++) {
        int idx = tid + i * 256;             // over 1024 float4
        int k = idx >> 4, d4 = (idx & 15) * 4;
        const float inv = sInv[k];
        float4 c = *(const float4*)&g_accC[prevB][k * DLAT + d4];
        c.x *= inv; c.y *= inv; c.z *= inv; c.w *= inv;
        *(uint4*)&sC[k * SC + d4] =
            make_uint4(tf32b(c.x), tf32b(c.y), tf32b(c.z), tf32b(c.w));
    }
    if (tid < KC) {
        const float inv = sInv[tid];
        float s = 0.f;
        const float4* cr = (const float4*)&g_accC[prevB][tid * DLAT];
#pragma unroll
        for (int i = 0; i < 16; i++) {
            float4 c = cr[i];
            float cx = c.x * inv, cy = c.y * inv, cz = c.z * inv, cw = c.w * inv;
            s += cx * cx + cy * cy + cz * cz + cw * cw;
        }
        sc2[tid] = s;
        srs[tid] = 0.f;
    }

    float acc2[4][4];
#pragma unroll
    for (int j = 0; j < 4; j++)
#pragma unroll
        for (int i = 0; i < 4; i++) acc2[j][i] = 0.f;
    float lossAcc = 0.f;

#pragma unroll 1
    for (int t = 0; t < TPB; t++) {
        const int rowBase = (blockIdx.x * TPB + t) * 128;
        __syncthreads();  // C stores (t=0) / previous GEMM2 reads done

        // ---- load enc tile as tf32 (stride SE) ----
        {
            const float4* src = (const float4*)(enc + (size_t)rowBase * DLAT);
#pragma unroll
            for (int i = 0; i < 8; i++) {
                int idx = tid + i * 256;     // over 2048 float4
                int row = idx >> 4, d4 = (idx & 15) * 4;
                float4 e = src[idx];
                *(uint4*)&sE[row * SE + d4] =
                    make_uint4(tf32b(e.x), tf32b(e.y), tf32b(e.z), tf32b(e.w));
            }
        }
        __syncthreads();

        // ---- GEMM1: rows [16w,16w+16) x 64 clusters, K=64 in 8 chunks ----
        float acc1[8][4];
#pragma unroll
        for (int n = 0; n < 8; n++)
#pragma unroll
            for (int i = 0; i < 4; i++) acc1[n][i] = 0.f;
        const int r0 = w * 16;
#pragma unroll
        for (int dc = 0; dc < 8; dc++) {
            uint32_t a[4];
            const int ab = (r0 + gid) * SE + dc * 8 + tig;
            a[0] = sE[ab];
            a[1] = sE[ab + 8 * SE];
            a[2] = sE[ab + 4];
            a[3] = sE[ab + 8 * SE + 4];
#pragma unroll
            for (int n = 0; n < 8; n++) {
                uint32_t b[2];
                const int bb = (n * 8 + gid) * SC + dc * 8 + tig;
                b[0] = sC[bb];
                b[1] = sC[bb + 4];
                mma8(acc1[n], a, b);
            }
        }

        // ---- epilogue: d2 in place of acc1, softmax (quad shuffle), loss,
        //      r -> sR (tf32), column sums ----
        {
            const int rowA = rowBase + r0 + gid;
            const float x2a = g_x2[rowA], x2b = g_x2[rowA + 8];
#pragma unroll
            for (int n = 0; n < 8; n++) {
                const float c20 = sc2[n * 8 + 2 * tig];
                const float c21 = sc2[n * 8 + 2 * tig + 1];
                float v;
                v = x2a + c20 - 2.f * acc1[n][0]; acc1[n][0] = v > 0.f ? v : 0.f;
                v = x2a + c21 - 2.f * acc1[n][1]; acc1[n][1] = v > 0.f ? v : 0.f;
                v = x2b + c20 - 2.f * acc1[n][2]; acc1[n][2] = v > 0.f ? v : 0.f;
                v = x2b + c21 - 2.f * acc1[n][3]; acc1[n][3] = v > 0.f ? v : 0.f;
            }
            float cs[16];
            const int rlA = r0 + gid;
            // two half-rows: h=0 -> rowA (acc1[n][0..1]), h=1 -> rowB (acc1[n][2..3])
#pragma unroll
            for (int h = 0; h < 2; h++) {
                float mn = 3.4e38f;
#pragma unroll
                for (int n = 0; n < 8; n++)
                    mn = fminf(mn, fminf(acc1[n][2 * h], acc1[n][2 * h + 1]));
                mn = fminf(mn, __shfl_xor_sync(0xffffffffu, mn, 1));
                mn = fminf(mn, __shfl_xor_sync(0xffffffffu, mn, 2));
                float es = 0.f;
#pragma unroll
                for (int n = 0; n < 8; n++)
                    es += __expf(mn - acc1[n][2 * h]) + __expf(mn - acc1[n][2 * h + 1]);
                es += __shfl_xor_sync(0xffffffffu, es, 1);
                es += __shfl_xor_sync(0xffffffffu, es, 2);
                const float inv = __fdividef(1.f, es);
                float ls = 0.f;
#pragma unroll
                for (int n = 0; n < 8; n++) {
                    float d20 = acc1[n][2 * h], d21 = acc1[n][2 * h + 1];
                    float rr0 = __expf(mn - d20) * inv;
                    float rr1 = __expf(mn - d21) * inv;
                    ls += rr0 * d20 + rr1 * d21;
                    if (h == 0) { cs[2 * n] = rr0; cs[2 * n + 1] = rr1; }
                    else        { cs[2 * n] += rr0; cs[2 * n + 1] += rr1; }
                    if (!doLoss)
                        *(uint2*)&sR[(rlA + 8 * h) * SR + n * 8 + 2 * tig] =
                            make_uint2(tf32b(rr0), tf32b(rr1));
                }
                if (doLoss) {
                    ls += __shfl_xor_sync(0xffffffffu, ls, 1);
                    ls += __shfl_xor_sync(0xffffffffu, ls, 2);
                    if (tig == 0) lossAcc += ls;
                }
            }
            if (!doLoss) {
                // column sums of r over this warp's 16 rows -> shared atomics
#pragma unroll
                for (int i = 0; i < 16; i++) {
                    cs[i] += __shfl_xor_sync(0xffffffffu, cs[i], 4);
                    cs[i] += __shfl_xor_sync(0xffffffffu, cs[i], 8);
                    cs[i] += __shfl_xor_sync(0xffffffffu, cs[i], 16);
                }
                if (gid == 0) {
#pragma unroll
                    for (int n = 0; n < 8; n++) {
                        atomicAdd(&srs[n * 8 + 2 * tig],     cs[2 * n]);
                        atomicAdd(&srs[n * 8 + 2 * tig + 1], cs[2 * n + 1]);
                    }
                }
            }
        }

        if (!doLoss) {
            __syncthreads();  // all r tiles written before GEMM2 reads

            // ---- GEMM2: clusters [(w&3)*16,+16) x d [(w>>2)*32,+32), K=128 ----
            const int m0 = (w & 3) * 16;
            const int nb4 = (w >> 2) * 4;
#pragma unroll
            for (int rc = 0; rc < 16; rc++) {
                uint32_t a[4];
                const int ar = (rc * 8 + tig) * SR + m0 + gid;
                const int ar4 = ar + 4 * SR;
                a[0] = sR[ar];
                a[1] = sR[ar + 8];
                a[2] = sR[ar4];
                a[3] = sR[ar4 + 8];
#pragma unroll
                for (int j = 0; j < 4; j++) {
                    uint32_t b[2];
                    const int be = (rc * 8 + tig) * SE + (nb4 + j) * 8 + gid;
                    b[0] = sE[be];
                    b[1] = sE[be + 4 * SE];
                    mma8(acc2[j], a, b);
                }
            }
        }
    }

    if (!doLoss) {
        // ---- accumulate partials via global atomics (no update kernel) ----
        const int m0 = (w & 3) * 16;
        const int nb4 = (w >> 2) * 4;
        float* accC = g_accC[curB];
#pragma unroll
        for (int j = 0; j < 4; j++) {
            const int n0 = (nb4 + j) * 8;
            const int kA = m0 + gid, kB = kA + 8;
            const int col = n0 + 2 * tig;
            atomicAdd(&accC[kA * DLAT + col],     acc2[j][0]);
            atomicAdd(&accC[kA * DLAT + col + 1], acc2[j][1]);
            atomicAdd(&accC[kB * DLAT + col],     acc2[j][2]);
            atomicAdd(&accC[kB * DLAT + col + 1], acc2[j][3]);
        }
        // srs finalized before the pre-GEMM2 barrier of the last tile
        if (tid < KC) atomicAdd(&g_accR[curB][tid], srs[tid]);
    } else {
        sred[tid] = lossAcc;
        __syncthreads();
        for (int o = 128; o > 0; o >>= 1) {
            if (tid < o) sred[tid] += sred[tid + o];
            __syncthreads();
        }
        if (tid == 0) atomicAdd(&g_lossSum, sred[0]);
    }
}

__global__ void finalize_kernel(float* out) {
    out[0] = g_decSum * (1.f / ((float)NROWS * (float)DDATA))
           + 0.001f * g_lossSum * (1.f / (float)NROWS);
}

// ---------------------------------------------------------------------------
extern "C" void kernel_launch(void* const* d_in, const int* in_sizes, int n_in,
                              void* d_out, int out_size) {
    const float* X   = (const float*)d_in[0];
    const float* enc = (const float*)d_in[1];
    const float* dec = (const float*)d_in[2];
    float* out = (float*)d_out;

    cudaFuncSetAttribute(kmeans_iter, cudaFuncAttributeMaxDynamicSharedMemorySize,
                         SM_TOTAL);

    init_kernel<<<NROWS / 256, 256>>>(enc);

    const int n4 = NROWS * DDATA / 4;
    decoder_kernel<<<1024, 256>>>((const float4*)X, (const float4*)dec, n4);

    for (int it = 0; it < NITERS; it++) {
        const int prevB = (it + 2) % 3;
        const int curB  = it % 3;
        const int zeroB = (it + 1) % 3;
        kmeans_iter<<<NB, 256, SM_TOTAL>>>(enc, prevB, curB, zeroB,
                                           it == NITERS - 1 ? 1 : 0);
    }

    finalize_kernel<<<1, 1>>>(out);
}

// round 15
// speedup vs baseline: 1.0809x; 1.0188x over previous
#include <cuda_runtime.h>
#include <cstdint>

// Problem constants (fixed shapes for ClusterLoss_82317343195278)
#define NROWS 65536
#define DLAT  64
#define KC    64
#define DDATA 512
#define NB    256   // kmeans blocks; TPB tiles of 128 rows each
#define TPB   2
#define NITERS 10

// ---- strides (in floats) ----
// SE=76: GEMM1 A (gid*76+tig -> gid*12+tig mod32 unique) AND GEMM2 B
//        (tig*76+gid -> tig*12+gid mod32 unique) both conflict-free.
#define SE 76
// SC=72 with k-pair permutation: within each 8-k chunk, storage order is
// [k0,k4,k1,k5,k2,k6,k3,k7], so the mma B pair (k=tig, k=tig+4) is one
// aligned LDS.64 at offset 2*tig. Banks: gid*8 + 2*tig mod 32 distinct.
#define SC 72
#define SR 72   // GEMM2 A: tig*72+gid -> tig*8+gid mod32 unique

// ---- dynamic smem layout (bytes) ----
#define SM_E    0u
#define SM_C    (SM_E + 128u * SE * 4u)          // 38912
#define SM_R    (SM_C + 64u * SC * 4u)           // 57344
#define SM_SC2  (SM_R + 128u * SR * 4u)          // 94208
#define SM_SRS  (SM_SC2 + 256u)                  // 94464
#define SM_SINV (SM_SRS + 256u)                  // 94720
#define SM_SRED (SM_SINV + 256u)                 // 94976
#define SM_TOTAL (SM_SRED + 1024u)               // 96000  (2 CTAs/SM)

// ---- tf32 helpers ----
__device__ __forceinline__ uint32_t tf32b(float x) {
    uint32_t u;
    asm("cvt.rna.tf32.f32 %0, %1;" : "=r"(u) : "f"(x));
    return u;
}
// mma.sync m16n8k8 tf32: D += A*B (D,C same regs)
__device__ __forceinline__ void mma8(float* d, const uint32_t* a, const uint32_t* b) {
    asm volatile(
        "mma.sync.aligned.m16n8k8.row.col.f32.tf32.tf32.f32 "
        "{%0,%1,%2,%3}, {%4,%5,%6,%7}, {%8,%9}, {%0,%1,%2,%3};"
        : "+f"(d[0]), "+f"(d[1]), "+f"(d[2]), "+f"(d[3])
        : "r"(a[0]), "r"(a[1]), "r"(a[2]), "r"(a[3]), "r"(b[0]), "r"(b[1]));
}

// ---- global scratch ----
// Triple-buffered centroid accumulators. Iter t: reads buf (t+2)%3,
// writes buf t%3, zeroes buf (t+1)%3 (consumed at iter t-1; kernel
// boundaries provide all ordering). Init seeds buf 2 (acc=enc[:K], den=1)
// and zeroes buf 0 (iter 0's output).
__device__ __align__(16) float g_accC[3][KC * DLAT];
__device__ float g_accR[3][KC];
__device__ __align__(16) float g_x2[NROWS];
__device__ float g_lossSum;
__device__ float g_decSum;

// ---------------------------------------------------------------------------
// Init: x2 per row, seed centroid buffers, zero scalars
// ---------------------------------------------------------------------------
__global__ void init_kernel(const float* __restrict__ enc) {
    int g = blockIdx.x * blockDim.x + threadIdx.x;  // one thread per row
    const float4* p = reinterpret_cast<const float4*>(enc) + (size_t)g * (DLAT / 4);
    float s = 0.f;
#pragma unroll
    for (int i = 0; i < DLAT / 4; i++) {
        float4 v = p[i];
        s += v.x * v.x + v.y * v.y + v.z * v.z + v.w * v.w;
    }
    g_x2[g] = s;
    if (g < KC * DLAT) {
        g_accC[2][g] = enc[g];   // seed: C0 = enc[:K]  (den=1 -> exact)
        g_accC[0][g] = 0.f;      // iter 0 output buffer
    }
    if (g < KC) {
        g_accR[2][g] = 1.0f;     // 1 + 1e-8f rounds to 1.0f in fp32
        g_accR[0][g] = 0.f;
    }
    if (g == 0) { g_lossSum = 0.f; g_decSum = 0.f; }
}

__global__ void decoder_kernel(const float4* __restrict__ X,
                               const float4* __restrict__ Dc, int n4) {
    int i = blockIdx.x * blockDim.x + threadIdx.x;
    int stride = gridDim.x * blockDim.x;
    float s = 0.f;
    for (; i < n4; i += stride) {
        float4 a = X[i], b = Dc[i];
        float dx = a.x - b.x, dy = a.y - b.y, dz = a.z - b.z, dw = a.w - b.w;
        s += dx * dx + dy * dy + dz * dz + dw * dw;
    }
    __shared__ float red[256];
    red[threadIdx.x] = s;
    __syncthreads();
#pragma unroll
    for (int o = 128; o > 0; o >>= 1) {
        if (threadIdx.x < o) red[threadIdx.x] += red[threadIdx.x + o];
        __syncthreads();
    }
    if (threadIdx.x == 0) atomicAdd(&g_decSum, red[0]);
}

// ---------------------------------------------------------------------------
// kmeans iteration: both GEMMs on mma.sync tf32, single-pass.
// C is materialized on the fly from accC[prev]/(accR[prev]+eps) into a
// k-pair-permuted smem layout (B fragments load as LDS.64).
// Output partials accumulated via global atomics into accC[cur]/accR[cur].
// Last iteration (doLoss): loss only, GEMM2/accumulation skipped.
// ---------------------------------------------------------------------------
__global__ void __launch_bounds__(256, 2)
kmeans_iter(const float* __restrict__ enc, int prevB, int curB, int zeroB,
            int doLoss) {
    extern __shared__ __align__(16) char smem[];
    uint32_t* sE = (uint32_t*)(smem + SM_E);
    uint32_t* sC = (uint32_t*)(smem + SM_C);
    uint32_t* sR = (uint32_t*)(smem + SM_R);
    float* sc2  = (float*)(smem + SM_SC2);
    float* srs  = (float*)(smem + SM_SRS);
    float* sInv = (float*)(smem + SM_SINV);
    float* sred = (float*)(smem + SM_SRED);

    const int tid = threadIdx.x;
    const int w = tid >> 5, lane = tid & 31;
    const int gid = lane >> 2, tig = lane & 3;

    // ---- zero next-iteration's accumulator slice (no ordering needed:
    //      zeroB was consumed one kernel ago, written one kernel ahead) ----
    if (tid < 16) g_accC[zeroB][blockIdx.x * 16 + tid] = 0.f;
    if (tid == 16 && blockIdx.x < KC) g_accR[zeroB][blockIdx.x] = 0.f;

    // ---- per-cluster inverse denominator ----
    if (tid < KC) sInv[tid] = __fdividef(1.f, g_accR[prevB][tid] + 1e-8f);
    __syncthreads();

    // ---- materialize C = accC*inv as tf32 into k-pair-permuted layout:
    //      chunk of 8 k-values stored as pairs (k,k+4) at offsets 0,2,4,6 ----
#pragma unroll
    for (int i = 0; i < 2; i++) {
        int ch = tid + i * 256;              // 512 chunks (64 k x 8 chunks)
        int k = ch >> 3, c8 = (ch & 7) << 3;
        const float inv = sInv[k];
        const float4* cp = (const float4*)&g_accC[prevB][k * DLAT + c8];
        float4 u = cp[0], v = cp[1];
        u.x *= inv; u.y *= inv; u.z *= inv; u.w *= inv;
        v.x *= inv; v.y *= inv; v.z *= inv; v.w *= inv;
        const uint32_t base = k * SC + c8;
        *(uint2*)&sC[base]     = make_uint2(tf32b(u.x), tf32b(v.x));
        *(uint2*)&sC[base + 2] = make_uint2(tf32b(u.y), tf32b(v.y));
        *(uint2*)&sC[base + 4] = make_uint2(tf32b(u.z), tf32b(v.z));
        *(uint2*)&sC[base + 6] = make_uint2(tf32b(u.w), tf32b(v.w));
    }
    if (tid < KC) {
        const float inv = sInv[tid];
        float s = 0.f;
        const float4* cr = (const float4*)&g_accC[prevB][tid * DLAT];
#pragma unroll
        for (int i = 0; i < 16; i++) {
            float4 c = cr[i];
            float cx = c.x * inv, cy = c.y * inv, cz = c.z * inv, cw = c.w * inv;
            s += cx * cx + cy * cy + cz * cz + cw * cw;
        }
        sc2[tid] = s;
        srs[tid] = 0.f;
    }

    float acc2[4][4];
#pragma unroll
    for (int j = 0; j < 4; j++)
#pragma unroll
        for (int i = 0; i < 4; i++) acc2[j][i] = 0.f;
    float lossAcc = 0.f;

#pragma unroll 1
    for (int t = 0; t < TPB; t++) {
        const int rowBase = (blockIdx.x * TPB + t) * 128;
        __syncthreads();  // C stores (t=0) / previous GEMM2 reads done

        // ---- load enc tile as tf32 (stride SE, natural k order) ----
        {
            const float4* src = (const float4*)(enc + (size_t)rowBase * DLAT);
#pragma unroll
            for (int i = 0; i < 8; i++) {
                int idx = tid + i * 256;     // over 2048 float4
                int row = idx >> 4, d4 = (idx & 15) * 4;
                float4 e = src[idx];
                *(uint4*)&sE[row * SE + d4] =
                    make_uint4(tf32b(e.x), tf32b(e.y), tf32b(e.z), tf32b(e.w));
            }
        }
        __syncthreads();

        // ---- GEMM1: rows [16w,16w+16) x 64 clusters, K=64 in 8 chunks ----
        float acc1[8][4];
#pragma unroll
        for (int n = 0; n < 8; n++)
#pragma unroll
            for (int i = 0; i < 4; i++) acc1[n][i] = 0.f;
        const int r0 = w * 16;
#pragma unroll
        for (int dc = 0; dc < 8; dc++) {
            uint32_t a[4];
            const int ab = (r0 + gid) * SE + dc * 8 + tig;
            a[0] = sE[ab];
            a[1] = sE[ab + 8 * SE];
            a[2] = sE[ab + 4];
            a[3] = sE[ab + 8 * SE + 4];
#pragma unroll
            for (int n = 0; n < 8; n++) {
                // permuted sC: (k=tig, k=tig+4) pair is one aligned LDS.64
                uint2 bp = *(const uint2*)&sC[(n * 8 + gid) * SC + dc * 8 + 2 * tig];
                uint32_t b[2] = { bp.x, bp.y };
                mma8(acc1[n], a, b);
            }
        }

        // ---- epilogue: d2 in acc1 -> exp cached in acc1; softmax via quad
        //      shuffles; loss or r/colsums ----
        {
            const int rowA = rowBase + r0 + gid;
            const float x2a = g_x2[rowA], x2b = g_x2[rowA + 8];
#pragma unroll
            for (int n = 0; n < 8; n++) {
                const float c20 = sc2[n * 8 + 2 * tig];
                const float c21 = sc2[n * 8 + 2 * tig + 1];
                float v;
                v = x2a + c20 - 2.f * acc1[n][0]; acc1[n][0] = v > 0.f ? v : 0.f;
                v = x2a + c21 - 2.f * acc1[n][1]; acc1[n][1] = v > 0.f ? v : 0.f;
                v = x2b + c20 - 2.f * acc1[n][2]; acc1[n][2] = v > 0.f ? v : 0.f;
                v = x2b + c21 - 2.f * acc1[n][3]; acc1[n][3] = v > 0.f ? v : 0.f;
            }
            float cs[16];
            const int rlA = r0 + gid;
            // two half-rows: h=0 -> rowA (acc1[n][0..1]), h=1 -> rowB (acc1[n][2..3])
#pragma unroll
            for (int h = 0; h < 2; h++) {
                float mn = 3.4e38f;
#pragma unroll
                for (int n = 0; n < 8; n++)
                    mn = fminf(mn, fminf(acc1[n][2 * h], acc1[n][2 * h + 1]));
                mn = fminf(mn, __shfl_xor_sync(0xffffffffu, mn, 1));
                mn = fminf(mn, __shfl_xor_sync(0xffffffffu, mn, 2));
                float es = 0.f, ed2 = 0.f;
#pragma unroll
                for (int n = 0; n < 8; n++) {
                    float d20 = acc1[n][2 * h], d21 = acc1[n][2 * h + 1];
                    float e0 = __expf(mn - d20);
                    float e1 = __expf(mn - d21);
                    es += e0 + e1;
                    ed2 += e0 * d20 + e1 * d21;
                    acc1[n][2 * h] = e0;      // cache exp; d2 no longer needed
                    acc1[n][2 * h + 1] = e1;
                }
                es += __shfl_xor_sync(0xffffffffu, es, 1);
                es += __shfl_xor_sync(0xffffffffu, es, 2);
                const float inv = __fdividef(1.f, es);
                if (doLoss) {
                    float ls = ed2 * inv;
                    ls += __shfl_xor_sync(0xffffffffu, ls, 1);
                    ls += __shfl_xor_sync(0xffffffffu, ls, 2);
                    if (tig == 0) lossAcc += ls;
                } else {
#pragma unroll
                    for (int n = 0; n < 8; n++) {
                        float rr0 = acc1[n][2 * h] * inv;
                        float rr1 = acc1[n][2 * h + 1] * inv;
                        if (h == 0) { cs[2 * n] = rr0; cs[2 * n + 1] = rr1; }
                        else        { cs[2 * n] += rr0; cs[2 * n + 1] += rr1; }
                        *(uint2*)&sR[(rlA + 8 * h) * SR + n * 8 + 2 * tig] =
                            make_uint2(tf32b(rr0), tf32b(rr1));
                    }
                }
            }
            if (!doLoss) {
                // column sums of r over this warp's 16 rows -> shared atomics
#pragma unroll
                for (int i = 0; i < 16; i++) {
                    cs[i] += __shfl_xor_sync(0xffffffffu, cs[i], 4);
                    cs[i] += __shfl_xor_sync(0xffffffffu, cs[i], 8);
                    cs[i] += __shfl_xor_sync(0xffffffffu, cs[i], 16);
                }
                if (gid == 0) {
#pragma unroll
                    for (int n = 0; n < 8; n++) {
                        atomicAdd(&srs[n * 8 + 2 * tig],     cs[2 * n]);
                        atomicAdd(&srs[n * 8 + 2 * tig + 1], cs[2 * n + 1]);
                    }
                }
            }
        }

        if (!doLoss) {
            __syncthreads();  // all r tiles written before GEMM2 reads

            // ---- GEMM2: clusters [(w&3)*16,+16) x d [(w>>2)*32,+32), K=128 ----
            const int m0 = (w & 3) * 16;
            const int nb4 = (w >> 2) * 4;
#pragma unroll
            for (int rc = 0; rc < 16; rc++) {
                uint32_t a[4];
                const int ar = (rc * 8 + tig) * SR + m0 + gid;
                const int ar4 = ar + 4 * SR;
                a[0] = sR[ar];
                a[1] = sR[ar + 8];
                a[2] = sR[ar4];
                a[3] = sR[ar4 + 8];
#pragma unroll
                for (int j = 0; j < 4; j++) {
                    uint32_t b[2];
                    const int be = (rc * 8 + tig) * SE + (nb4 + j) * 8 + gid;
                    b[0] = sE[be];
                    b[1] = sE[be + 4 * SE];
                    mma8(acc2[j], a, b);
                }
            }
        }
    }

    if (!doLoss) {
        // ---- accumulate partials via global atomics (no update kernel) ----
        const int m0 = (w & 3) * 16;
        const int nb4 = (w >> 2) * 4;
        float* accC = g_accC[curB];
#pragma unroll
        for (int j = 0; j < 4; j++) {
            const int n0 = (nb4 + j) * 8;
            const int kA = m0 + gid, kB = kA + 8;
            const int col = n0 + 2 * tig;
            atomicAdd(&accC[kA * DLAT + col],     acc2[j][0]);
            atomicAdd(&accC[kA * DLAT + col + 1], acc2[j][1]);
            atomicAdd(&accC[kB * DLAT + col],     acc2[j][2]);
            atomicAdd(&accC[kB * DLAT + col + 1], acc2[j][3]);
        }
        // srs finalized before the pre-GEMM2 barrier of the last tile
        if (tid < KC) atomicAdd(&g_accR[curB][tid], srs[tid]);
    } else {
        sred[tid] = lossAcc;
        __syncthreads();
        for (int o = 128; o > 0; o >>= 1) {
            if (tid < o) sred[tid] += sred[tid + o];
            __syncthreads();
        }
        if (tid == 0) atomicAdd(&g_lossSum, sred[0]);
    }
}

__global__ void finalize_kernel(float* out) {
    out[0] = g_decSum * (1.f / ((float)NROWS * (float)DDATA))
           + 0.001f * g_lossSum * (1.f / (float)NROWS);
}

// ---------------------------------------------------------------------------
extern "C" void kernel_launch(void* const* d_in, const int* in_sizes, int n_in,
                              void* d_out, int out_size) {
    const float* X   = (const float*)d_in[0];
    const float* enc = (const float*)d_in[1];
    const float* dec = (const float*)d_in[2];
    float* out = (float*)d_out;

    cudaFuncSetAttribute(kmeans_iter, cudaFuncAttributeMaxDynamicSharedMemorySize,
                         SM_TOTAL);

    init_kernel<<<NROWS / 256, 256>>>(enc);

    const int n4 = NROWS * DDATA / 4;
    decoder_kernel<<<1024, 256>>>((const float4*)X, (const float4*)dec, n4);

    for (int it = 0; it < NITERS; it++) {
        const int prevB = (it + 2) % 3;
        const int curB  = it % 3;
        const int zeroB = (it + 1) % 3;
        kmeans_iter<<<NB, 256, SM_TOTAL>>>(enc, prevB, curB, zeroB,
                                           it == NITERS - 1 ? 1 : 0);
    }

    finalize_kernel<<<1, 1>>>(out);
}

// round 16
// speedup vs baseline: 1.0918x; 1.0101x over previous
#include <cuda_runtime.h>
#include <cstdint>

// Problem constants (fixed shapes for ClusterLoss_82317343195278)
#define NROWS 65536
#define DLAT  64
#define KC    64
#define DDATA 512
#define NB    256   // kmeans blocks; TPB tiles of 128 rows each
#define TPB   2
#define NITERS 10

// ---- strides (in floats) ----
// SE=76: GEMM1 A (gid*76+tig -> gid*12+tig mod32 unique) AND GEMM2 B
//        (tig*76+gid -> tig*12+gid mod32 unique) both conflict-free.
#define SE 76
// SC=72 with k-pair permutation: within each 8-k chunk, storage order is
// [k0,k4,k1,k5,k2,k6,k3,k7], so the mma B pair (k=tig, k=tig+4) is one
// aligned LDS.64 at offset 2*tig. Banks: gid*8 + 2*tig mod 32 distinct.
#define SC 72
#define SR 72   // GEMM2 A: tig*72+gid -> tig*8+gid mod32 unique

// ---- dynamic smem layout (bytes) ----
#define SM_E    0u
#define SM_C    (SM_E + 128u * SE * 4u)          // 38912
#define SM_R    (SM_C + 64u * SC * 4u)           // 57344
#define SM_SC2  (SM_R + 128u * SR * 4u)          // 94208
#define SM_SRS  (SM_SC2 + 256u)                  // 94464
#define SM_SINV (SM_SRS + 256u)                  // 94720
#define SM_SRED (SM_SINV + 256u)                 // 94976
#define SM_TOTAL (SM_SRED + 1024u)               // 96000  (2 CTAs/SM)

// ---- tf32 helpers ----
__device__ __forceinline__ uint32_t tf32b(float x) {
    uint32_t u;
    asm("cvt.rna.tf32.f32 %0, %1;" : "=r"(u) : "f"(x));
    return u;
}
// mma.sync m16n8k8 tf32: D += A*B (D,C same regs)
__device__ __forceinline__ void mma8(float* d, const uint32_t* a, const uint32_t* b) {
    asm volatile(
        "mma.sync.aligned.m16n8k8.row.col.f32.tf32.tf32.f32 "
        "{%0,%1,%2,%3}, {%4,%5,%6,%7}, {%8,%9}, {%0,%1,%2,%3};"
        : "+f"(d[0]), "+f"(d[1]), "+f"(d[2]), "+f"(d[3])
        : "r"(a[0]), "r"(a[1]), "r"(a[2]), "r"(a[3]), "r"(b[0]), "r"(b[1]));
}

// ---- global scratch ----
// Triple-buffered centroid accumulators. Iter t: reads buf (t+2)%3,
// writes buf t%3, zeroes buf (t+1)%3 (consumed at iter t-1; kernel
// boundaries provide all ordering). Init seeds buf 2 (acc=enc[:K], den=1)
// and zeroes buf 0 (iter 0's output).
__device__ __align__(16) float g_accC[3][KC * DLAT];
__device__ float g_accR[3][KC];
__device__ __align__(16) float g_x2[NROWS];
__device__ float g_lossSum;
__device__ float g_decSum;

// ---------------------------------------------------------------------------
// Init: x2 per row, seed centroid buffers, zero scalars
// ---------------------------------------------------------------------------
__global__ void init_kernel(const float* __restrict__ enc) {
    int g = blockIdx.x * blockDim.x + threadIdx.x;  // one thread per row
    const float4* p = reinterpret_cast<const float4*>(enc) + (size_t)g * (DLAT / 4);
    float s = 0.f;
#pragma unroll
    for (int i = 0; i < DLAT / 4; i++) {
        float4 v = p[i];
        s += v.x * v.x + v.y * v.y + v.z * v.z + v.w * v.w;
    }
    g_x2[g] = s;
    if (g < KC * DLAT) {
        g_accC[2][g] = enc[g];   // seed: C0 = enc[:K]  (den=1 -> exact)
        g_accC[0][g] = 0.f;      // iter 0 output buffer
    }
    if (g < KC) {
        g_accR[2][g] = 1.0f;     // 1 + 1e-8f rounds to 1.0f in fp32
        g_accR[0][g] = 0.f;
    }
    if (g == 0) { g_lossSum = 0.f; g_decSum = 0.f; }
}

// ---------------------------------------------------------------------------
// Decoder loss: runs on a forked side stream, concurrent with the kmeans
// chain (kmeans leaves ~91% of DRAM bandwidth and the 40 single-CTA SMs idle).
// ---------------------------------------------------------------------------
__global__ void decoder_kernel(const float4* __restrict__ X,
                               const float4* __restrict__ Dc, int n4) {
    int i = blockIdx.x * blockDim.x + threadIdx.x;
    int stride = gridDim.x * blockDim.x;
    float s = 0.f;
    for (; i < n4; i += stride) {
        float4 a = X[i], b = Dc[i];
        float dx = a.x - b.x, dy = a.y - b.y, dz = a.z - b.z, dw = a.w - b.w;
        s += dx * dx + dy * dy + dz * dz + dw * dw;
    }
    __shared__ float red[256];
    red[threadIdx.x] = s;
    __syncthreads();
#pragma unroll
    for (int o = 128; o > 0; o >>= 1) {
        if (threadIdx.x < o) red[threadIdx.x] += red[threadIdx.x + o];
        __syncthreads();
    }
    if (threadIdx.x == 0) atomicAdd(&g_decSum, red[0]);
}

// ---------------------------------------------------------------------------
// kmeans iteration: both GEMMs on mma.sync tf32, single-pass.
// C is materialized on the fly from accC[prev]/(accR[prev]+eps) into a
// k-pair-permuted smem layout (B fragments load as LDS.64).
// Output partials accumulated via global atomics into accC[cur]/accR[cur].
// Last iteration (doLoss): loss only, GEMM2/accumulation skipped.
// ---------------------------------------------------------------------------
__global__ void __launch_bounds__(256, 2)
kmeans_iter(const float* __restrict__ enc, int prevB, int curB, int zeroB,
            int doLoss) {
    extern __shared__ __align__(16) char smem[];
    uint32_t* sE = (uint32_t*)(smem + SM_E);
    uint32_t* sC = (uint32_t*)(smem + SM_C);
    uint32_t* sR = (uint32_t*)(smem + SM_R);
    float* sc2  = (float*)(smem + SM_SC2);
    float* srs  = (float*)(smem + SM_SRS);
    float* sInv = (float*)(smem + SM_SINV);
    float* sred = (float*)(smem + SM_SRED);

    const int tid = threadIdx.x;
    const int w = tid >> 5, lane = tid & 31;
    const int gid = lane >> 2, tig = lane & 3;

    // ---- zero next-iteration's accumulator slice (no ordering needed:
    //      zeroB was consumed one kernel ago, written one kernel ahead) ----
    if (tid < 16) g_accC[zeroB][blockIdx.x * 16 + tid] = 0.f;
    if (tid == 16 && blockIdx.x < KC) g_accR[zeroB][blockIdx.x] = 0.f;

    // ---- per-cluster inverse denominator ----
    if (tid < KC) sInv[tid] = __fdividef(1.f, g_accR[prevB][tid] + 1e-8f);
    __syncthreads();

    // ---- materialize C = accC*inv as tf32 into k-pair-permuted layout:
    //      chunk of 8 k-values stored as pairs (k,k+4) at offsets 0,2,4,6 ----
#pragma unroll
    for (int i = 0; i < 2; i++) {
        int ch = tid + i * 256;              // 512 chunks (64 k x 8 chunks)
        int k = ch >> 3, c8 = (ch & 7) << 3;
        const float inv = sInv[k];
        const float4* cp = (const float4*)&g_accC[prevB][k * DLAT + c8];
        float4 u = cp[0], v = cp[1];
        u.x *= inv; u.y *= inv; u.z *= inv; u.w *= inv;
        v.x *= inv; v.y *= inv; v.z *= inv; v.w *= inv;
        const uint32_t base = k * SC + c8;
        *(uint2*)&sC[base]     = make_uint2(tf32b(u.x), tf32b(v.x));
        *(uint2*)&sC[base + 2] = make_uint2(tf32b(u.y), tf32b(v.y));
        *(uint2*)&sC[base + 4] = make_uint2(tf32b(u.z), tf32b(v.z));
        *(uint2*)&sC[base + 6] = make_uint2(tf32b(u.w), tf32b(v.w));
    }
    if (tid < KC) {
        const float inv = sInv[tid];
        float s = 0.f;
        const float4* cr = (const float4*)&g_accC[prevB][tid * DLAT];
#pragma unroll
        for (int i = 0; i < 16; i++) {
            float4 c = cr[i];
            float cx = c.x * inv, cy = c.y * inv, cz = c.z * inv, cw = c.w * inv;
            s += cx * cx + cy * cy + cz * cz + cw * cw;
        }
        sc2[tid] = s;
        srs[tid] = 0.f;
    }

    float acc2[4][4];
#pragma unroll
    for (int j = 0; j < 4; j++)
#pragma unroll
        for (int i = 0; i < 4; i++) acc2[j][i] = 0.f;
    float lossAcc = 0.f;

#pragma unroll 1
    for (int t = 0; t < TPB; t++) {
        const int rowBase = (blockIdx.x * TPB + t) * 128;
        __syncthreads();  // C stores (t=0) / previous GEMM2 reads done

        // ---- load enc tile as tf32 (stride SE, natural k order) ----
        {
            const float4* src = (const float4*)(enc + (size_t)rowBase * DLAT);
#pragma unroll
            for (int i = 0; i < 8; i++) {
                int idx = tid + i * 256;     // over 2048 float4
                int row = idx >> 4, d4 = (idx & 15) * 4;
                float4 e = src[idx];
                *(uint4*)&sE[row * SE + d4] =
                    make_uint4(tf32b(e.x), tf32b(e.y), tf32b(e.z), tf32b(e.w));
            }
        }
        __syncthreads();

        // ---- GEMM1: rows [16w,16w+16) x 64 clusters, K=64 in 8 chunks ----
        float acc1[8][4];
#pragma unroll
        for (int n = 0; n < 8; n++)
#pragma unroll
            for (int i = 0; i < 4; i++) acc1[n][i] = 0.f;
        const int r0 = w * 16;
#pragma unroll
        for (int dc = 0; dc < 8; dc++) {
            uint32_t a[4];
            const int ab = (r0 + gid) * SE + dc * 8 + tig;
            a[0] = sE[ab];
            a[1] = sE[ab + 8 * SE];
            a[2] = sE[ab + 4];
            a[3] = sE[ab + 8 * SE + 4];
#pragma unroll
            for (int n = 0; n < 8; n++) {
                // permuted sC: (k=tig, k=tig+4) pair is one aligned LDS.64
                uint2 bp = *(const uint2*)&sC[(n * 8 + gid) * SC + dc * 8 + 2 * tig];
                uint32_t b[2] = { bp.x, bp.y };
                mma8(acc1[n], a, b);
            }
        }

        // ---- epilogue: d2 in acc1 -> exp cached in acc1; softmax via quad
        //      shuffles; loss or r/colsums ----
        {
            const int rowA = rowBase + r0 + gid;
            const float x2a = g_x2[rowA], x2b = g_x2[rowA + 8];
#pragma unroll
            for (int n = 0; n < 8; n++) {
                const float c20 = sc2[n * 8 + 2 * tig];
                const float c21 = sc2[n * 8 + 2 * tig + 1];
                float v;
                v = x2a + c20 - 2.f * acc1[n][0]; acc1[n][0] = v > 0.f ? v : 0.f;
                v = x2a + c21 - 2.f * acc1[n][1]; acc1[n][1] = v > 0.f ? v : 0.f;
                v = x2b + c20 - 2.f * acc1[n][2]; acc1[n][2] = v > 0.f ? v : 0.f;
                v = x2b + c21 - 2.f * acc1[n][3]; acc1[n][3] = v > 0.f ? v : 0.f;
            }
            float cs[16];
            const int rlA = r0 + gid;
            // two half-rows: h=0 -> rowA (acc1[n][0..1]), h=1 -> rowB (acc1[n][2..3])
#pragma unroll
            for (int h = 0; h < 2; h++) {
                float mn = 3.4e38f;
#pragma unroll
                for (int n = 0; n < 8; n++)
                    mn = fminf(mn, fminf(acc1[n][2 * h], acc1[n][2 * h + 1]));
                mn = fminf(mn, __shfl_xor_sync(0xffffffffu, mn, 1));
                mn = fminf(mn, __shfl_xor_sync(0xffffffffu, mn, 2));
                float es = 0.f, ed2 = 0.f;
#pragma unroll
                for (int n = 0; n < 8; n++) {
                    float d20 = acc1[n][2 * h], d21 = acc1[n][2 * h + 1];
                    float e0 = __expf(mn - d20);
                    float e1 = __expf(mn - d21);
                    es += e0 + e1;
                    ed2 += e0 * d20 + e1 * d21;
                    acc1[n][2 * h] = e0;      // cache exp; d2 no longer needed
                    acc1[n][2 * h + 1] = e1;
                }
                es += __shfl_xor_sync(0xffffffffu, es, 1);
                es += __shfl_xor_sync(0xffffffffu, es, 2);
                const float inv = __fdividef(1.f, es);
                if (doLoss) {
                    float ls = ed2 * inv;
                    ls += __shfl_xor_sync(0xffffffffu, ls, 1);
                    ls += __shfl_xor_sync(0xffffffffu, ls, 2);
                    if (tig == 0) lossAcc += ls;
                } else {
#pragma unroll
                    for (int n = 0; n < 8; n++) {
                        float rr0 = acc1[n][2 * h] * inv;
                        float rr1 = acc1[n][2 * h + 1] * inv;
                        if (h == 0) { cs[2 * n] = rr0; cs[2 * n + 1] = rr1; }
                        else        { cs[2 * n] += rr0; cs[2 * n + 1] += rr1; }
                        *(uint2*)&sR[(rlA + 8 * h) * SR + n * 8 + 2 * tig] =
                            make_uint2(tf32b(rr0), tf32b(rr1));
                    }
                }
            }
            if (!doLoss) {
                // column sums of r over this warp's 16 rows -> shared atomics
#pragma unroll
                for (int i = 0; i < 16; i++) {
                    cs[i] += __shfl_xor_sync(0xffffffffu, cs[i], 4);
                    cs[i] += __shfl_xor_sync(0xffffffffu, cs[i], 8);
                    cs[i] += __shfl_xor_sync(0xffffffffu, cs[i], 16);
                }
                if (gid == 0) {
#pragma unroll
                    for (int n = 0; n < 8; n++) {
                        atomicAdd(&srs[n * 8 + 2 * tig],     cs[2 * n]);
                        atomicAdd(&srs[n * 8 + 2 * tig + 1], cs[2 * n + 1]);
                    }
                }
            }
        }

        if (!doLoss) {
            __syncthreads();  // all r tiles written before GEMM2 reads

            // ---- GEMM2: clusters [(w&3)*16,+16) x d [(w>>2)*32,+32), K=128 ----
            const int m0 = (w & 3) * 16;
            const int nb4 = (w >> 2) * 4;
#pragma unroll
            for (int rc = 0; rc < 16; rc++) {
                uint32_t a[4];
                const int ar = (rc * 8 + tig) * SR + m0 + gid;
                const int ar4 = ar + 4 * SR;
                a[0] = sR[ar];
                a[1] = sR[ar + 8];
                a[2] = sR[ar4];
                a[3] = sR[ar4 + 8];
#pragma unroll
                for (int j = 0; j < 4; j++) {
                    uint32_t b[2];
                    const int be = (rc * 8 + tig) * SE + (nb4 + j) * 8 + gid;
                    b[0] = sE[be];
                    b[1] = sE[be + 4 * SE];
                    mma8(acc2[j], a, b);
                }
            }
        }
    }

    if (!doLoss) {
        // ---- accumulate partials via global atomics (no update kernel) ----
        const int m0 = (w & 3) * 16;
        const int nb4 = (w >> 2) * 4;
        float* accC = g_accC[curB];
#pragma unroll
        for (int j = 0; j < 4; j++) {
            const int n0 = (nb4 + j) * 8;
            const int kA = m0 + gid, kB = kA + 8;
            const int col = n0 + 2 * tig;
            atomicAdd(&accC[kA * DLAT + col],     acc2[j][0]);
            atomicAdd(&accC[kA * DLAT + col + 1], acc2[j][1]);
            atomicAdd(&accC[kB * DLAT + col],     acc2[j][2]);
            atomicAdd(&accC[kB * DLAT + col + 1], acc2[j][3]);
        }
        // srs finalized before the pre-GEMM2 barrier of the last tile
        if (tid < KC) atomicAdd(&g_accR[curB][tid], srs[tid]);
    } else {
        sred[tid] = lossAcc;
        __syncthreads();
        for (int o = 128; o > 0; o >>= 1) {
            if (tid < o) sred[tid] += sred[tid + o];
            __syncthreads();
        }
        if (tid == 0) atomicAdd(&g_lossSum, sred[0]);
    }
}

__global__ void finalize_kernel(float* out) {
    out[0] = g_decSum * (1.f / ((float)NROWS * (float)DDATA))
           + 0.001f * g_lossSum * (1.f / (float)NROWS);
}

// ---------------------------------------------------------------------------
// Launch graph:  init -> { kmeans_0 .. kmeans_9 (default stream)
//                          || decoder (side stream) } -> finalize
// Fork/join via events; during stream capture these become graph edges
// (the documented multi-branch capture pattern). The side stream and events
// are host-side resources created once — no device allocation, and the work
// recorded per call is identical and deterministic.
// ---------------------------------------------------------------------------
extern "C" void kernel_launch(void* const* d_in, const int* in_sizes, int n_in,
                              void* d_out, int out_size) {
    const float* X   = (const float*)d_in[0];
    const float* enc = (const float*)d_in[1];
    const float* dec = (const float*)d_in[2];
    float* out = (float*)d_out;

    static cudaStream_t sideStream = []() {
        cudaStream_t s;
        cudaStreamCreateWithFlags(&s, cudaStreamNonBlocking);
        return s;
    }();
    static cudaEvent_t evFork = []() {
        cudaEvent_t e;
        cudaEventCreateWithFlags(&e, cudaEventDisableTiming);
        return e;
    }();
    static cudaEvent_t evJoin = []() {
        cudaEvent_t e;
        cudaEventCreateWithFlags(&e, cudaEventDisableTiming);
        return e;
    }();

    cudaFuncSetAttribute(kmeans_iter, cudaFuncAttributeMaxDynamicSharedMemorySize,
                         SM_TOTAL);

    init_kernel<<<NROWS / 256, 256>>>(enc);

    // fork: decoder runs concurrently with the kmeans chain
    cudaEventRecord(evFork, 0);
    cudaStreamWaitEvent(sideStream, evFork, 0);
    const int n4 = NROWS * DDATA / 4;
    decoder_kernel<<<1024, 256, 0, sideStream>>>((const float4*)X,
                                                 (const float4*)dec, n4);
    cudaEventRecord(evJoin, sideStream);

    for (int it = 0; it < NITERS; it++) {
        const int prevB = (it + 2) % 3;
        const int curB  = it % 3;
        const int zeroB = (it + 1) % 3;
        kmeans_iter<<<NB, 256, SM_TOTAL>>>(enc, prevB, curB, zeroB,
                                           it == NITERS - 1 ? 1 : 0);
    }

    // join: finalize needs g_decSum
    cudaStreamWaitEvent(0, evJoin, 0);
    finalize_kernel<<<1, 1>>>(out);
}